// round 17
// baseline (speedup 1.0000x reference)
#include <cuda_runtime.h>
#include <cuda_bf16.h>
#include <cuda_fp16.h>
#include <cstdint>

// ---------------------------------------------------------------------------
// AttentionS2: B=1, C=512, HEADS=8, hd=64, tokens HW=4096
// convert (x + all 4 weights -> fp16; lqw prescale) ->
// qkv GEMM (fp16) -> flash attn (fp16 QK/PV; MUFU ex2 softmax) ->
// out_proj (fp16 single-term, 256 CTAs, pipelined).
// ---------------------------------------------------------------------------

#define NTOK 4096
#define CIN  512
#define HEADS 8
#define HD 64

// preconverted inputs
__device__ __half g_xf[CIN * NTOK];            // x fp16 [cin][tok]
__device__ __half g_wf[4 * CIN * CIN];         // q,k,v,p weights fp16 [o][c]
__device__ float g_lq2[NTOK];   // lqw*log2e + 4*log2e (fixed-shift, base-2 domain)
// projections + attention output: fp16 (token-major)
__device__ __half g_qf[NTOK * CIN];
__device__ __half g_kf[NTOK * CIN];
__device__ __half g_vf[NTOK * CIN];
__device__ __half g_of[NTOK * CIN];

__device__ __forceinline__ float ex2f(float x) {
    float y;
    asm("ex2.approx.ftz.f32 %0, %1;" : "=f"(y) : "f"(x));
    return y;
}

__device__ __forceinline__ uint32_t packf16(float v0, float v1) {
    uint32_t r;
    asm("cvt.rn.f16x2.f32 %0, %1, %2;" : "=r"(r) : "f"(v1), "f"(v0));
    return r;
}

__device__ __forceinline__ void mma_f16(float* c, const uint32_t* a, uint32_t b0, uint32_t b1) {
    asm("mma.sync.aligned.m16n8k16.row.col.f32.f16.f16.f32 "
        "{%0,%1,%2,%3},{%4,%5,%6,%7},{%8,%9},{%0,%1,%2,%3};"
        : "+f"(c[0]), "+f"(c[1]), "+f"(c[2]), "+f"(c[3])
        : "r"(a[0]), "r"(a[1]), "r"(a[2]), "r"(a[3]), "r"(b0), "r"(b1));
}

__device__ __forceinline__ uint32_t smem_u32(const void* p) {
    return (uint32_t)__cvta_generic_to_shared(p);
}
__device__ __forceinline__ uint4 ldsm_x4(uint32_t addr) {
    uint4 r;
    asm("ldmatrix.sync.aligned.m8n8.x4.shared.b16 {%0,%1,%2,%3}, [%4];"
        : "=r"(r.x), "=r"(r.y), "=r"(r.z), "=r"(r.w) : "r"(addr));
    return r;
}
__device__ __forceinline__ uint4 ldsm_x4t(uint32_t addr) {
    uint4 r;
    asm("ldmatrix.sync.aligned.m8n8.x4.trans.shared.b16 {%0,%1,%2,%3}, [%4];"
        : "=r"(r.x), "=r"(r.y), "=r"(r.z), "=r"(r.w) : "r"(addr));
    return r;
}
__device__ __forceinline__ void cp16(uint32_t dst, const void* src) {
    asm volatile("cp.async.cg.shared.global [%0], [%1], 16;" :: "r"(dst), "l"(src));
}
__device__ __forceinline__ void cp4(uint32_t dst, const void* src) {
    asm volatile("cp.async.ca.shared.global [%0], [%1], 4;" :: "r"(dst), "l"(src));
}
__device__ __forceinline__ void cp_commit() {
    asm volatile("cp.async.commit_group;");
}
template <int N>
__device__ __forceinline__ void cp_wait() {
    asm volatile("cp.async.wait_group %0;" :: "n"(N));
}

// ---------------------------------------------------------------------------
// Kernel 0: one-shot conversion: x,qw,kw,vw,pw -> fp16; lqw -> base-2 prescale
// ---------------------------------------------------------------------------
#define NXF4 (CIN * NTOK / 4)   // 524288
#define NWF4 (CIN * CIN / 4)    // 65536
#define NLQ4 (NTOK / 4)         // 1024
#define NCONV (NXF4 + 4 * NWF4 + NLQ4)

__global__ __launch_bounds__(256)
void convert_kernel(const float* __restrict__ x,
                    const float* __restrict__ qw, const float* __restrict__ kw,
                    const float* __restrict__ vw, const float* __restrict__ pw,
                    const float* __restrict__ lqw)
{
    int i = blockIdx.x * 256 + threadIdx.x;
    if (i < NXF4) {
        float4 v = ((const float4*)x)[i];
        uint2 r; r.x = packf16(v.x, v.y); r.y = packf16(v.z, v.w);
        ((uint2*)g_xf)[i] = r;
        return;
    }
    int j = i - NXF4;
    if (j < 4 * NWF4) {
        int wsel = j >> 16;          // NWF4 = 2^16
        int k = j & (NWF4 - 1);
        const float* wp = (wsel == 0) ? qw : (wsel == 1) ? kw : (wsel == 2) ? vw : pw;
        float4 v = ((const float4*)wp)[k];
        uint2 r; r.x = packf16(v.x, v.y); r.y = packf16(v.z, v.w);
        ((uint2*)g_wf)[(size_t)wsel * NWF4 + k] = r;
        return;
    }
    j -= 4 * NWF4;
    if (j < NLQ4) {
        float4 v = ((const float4*)lqw)[j];
        float4 r;
        r.x = fmaf(v.x, 1.4426950408889634f, 5.770780163555853f);
        r.y = fmaf(v.y, 1.4426950408889634f, 5.770780163555853f);
        r.z = fmaf(v.z, 1.4426950408889634f, 5.770780163555853f);
        r.w = fmaf(v.w, 1.4426950408889634f, 5.770780163555853f);
        ((float4*)g_lq2)[j] = r;
    }
}

// ---------------------------------------------------------------------------
// Kernel 1: QKV projection, single fp16, 2-stage cp.async. (unchanged)
// ---------------------------------------------------------------------------
#define QKV_BWF 8704
#define QKV_STAGE 18944
#define QKV_SMEM_BYTES (2 * QKV_STAGE)   // 37888

__global__ __launch_bounds__(256, 2)
void qkv_proj_kernel(const float* __restrict__ qb, const float* __restrict__ kb,
                     const float* __restrict__ vb)
{
    extern __shared__ uint16_t qsm[];
    const uint32_t smb = smem_u32(qsm);

    const int tid  = threadIdx.x;
    const int lane = tid & 31, w = tid >> 5;
    const int g = lane >> 2, tig = lane & 3;
    const int wm = w & 3, wn = w >> 2;
    const int t0 = blockIdx.x * 128;
    const int nt = blockIdx.y;           // 0..11
    const int which = nt >> 2;           // 0=q 1=k 2=v
    const int o0 = (nt & 3) * 128;

    const size_t wbase = (size_t)which * CIN * CIN;
    const float* bia = (which == 0) ? qb : (which == 1) ? kb : vb;
    uint16_t* ovf = (uint16_t*)((which == 0) ? g_qf : (which == 1) ? g_kf : g_vf);

    const int arow = ((lane >> 4) & 1) * 8 + (lane & 7);
    const int acol = wm * 32 + ((lane >> 3) & 1) * 8;
    const int brow = ((lane >> 4) & 1) * 8 + (lane & 7);
    const int bcol = ((lane >> 3) & 1) * 8;

    float C[2][8][4] = {};

    auto stage = [&](uint32_t sb, int k0) {
        #pragma unroll
        for (int u = 0; u < 2; u++) {
            int idx = tid + u * 256;
            int row = idx >> 4, c4 = idx & 15;
            size_t gofs = (size_t)(k0 + row) * NTOK + t0 + c4 * 8;
            uint32_t so = (uint32_t)((row * 136 + c4 * 8) * 2);
            cp16(sb + so, (const uint16_t*)g_xf + gofs);
        }
        #pragma unroll
        for (int u = 0; u < 2; u++) {
            int idx = tid + u * 256;
            int row = idx >> 2, c4 = idx & 3;
            size_t gofs = wbase + (size_t)(o0 + row) * CIN + k0 + c4 * 8;
            uint32_t so = (uint32_t)((row * 40 + c4 * 8) * 2);
            cp16(sb + QKV_BWF + so, (const uint16_t*)g_wf + gofs);
        }
    };

    stage(smb, 0);
    cp_commit();

    for (int ki = 0; ki < 16; ki++) {
        __syncthreads();
        if (ki + 1 < 16) {
            stage(smb + ((ki + 1) & 1) * QKV_STAGE, (ki + 1) * 32);
            cp_commit();
            cp_wait<1>();
        } else {
            cp_wait<0>();
        }
        __syncthreads();

        const uint32_t sb = smb + (ki & 1) * QKV_STAGE;
        const uint32_t axf = sb, bwf = sb + QKV_BWF;

        #pragma unroll
        for (int ks = 0; ks < 2; ks++) {
            uint32_t A[2][4];
            #pragma unroll
            for (int mf = 0; mf < 2; mf++) {
                uint32_t off = (uint32_t)(((ks * 16 + arow) * 136 + acol + mf * 16) * 2);
                uint4 a = ldsm_x4t(axf + off);
                A[mf][0] = a.x; A[mf][1] = a.y; A[mf][2] = a.z; A[mf][3] = a.w;
            }
            #pragma unroll
            for (int np = 0; np < 4; np++) {
                uint32_t off = (uint32_t)(((wn * 64 + np * 16 + brow) * 40 + ks * 16 + bcol) * 2);
                uint4 B = ldsm_x4(bwf + off);
                #pragma unroll
                for (int mf = 0; mf < 2; mf++) {
                    mma_f16(C[mf][2*np],   A[mf], B.x, B.y);
                    mma_f16(C[mf][2*np+1], A[mf], B.z, B.w);
                }
            }
        }
    }

    #pragma unroll
    for (int mf = 0; mf < 2; mf++) {
        int r0 = t0 + wm * 32 + mf * 16 + g;
        #pragma unroll
        for (int n = 0; n < 8; n++) {
            int col = o0 + wn * 64 + n * 8 + 2 * tig;
            float b0 = bia[col], b1 = bia[col + 1];
            const float* c = C[mf][n];
            *(uint32_t*)(ovf + (size_t)r0 * CIN + col)       = packf16(c[0] + b0, c[1] + b1);
            *(uint32_t*)(ovf + (size_t)(r0 + 8) * CIN + col) = packf16(c[2] + b0, c[3] + b1);
        }
    }
}

// ---------------------------------------------------------------------------
// Kernel 2: flash attention, 128q x 128k, 2-stage cp.async, occ 2.
// QK/PV fp16. Softmax: MUFU ex2 (all lanes). Epilogue: o as fp16.
// ---------------------------------------------------------------------------
#define ATT_STG 36864
#define ATT_VF  18432
#define ATT_Q   73728
#define ATT_LQ  92160
#define ATTN_SMEM_BYTES (92160 + 1024)   // 93184

#define SCALE_LOG2E 0.18033688011112042f   // 0.125 * log2(e)

__global__ __launch_bounds__(256, 2)
void attn_kernel()
{
    extern __shared__ uint16_t sm16[];

    const int tid  = threadIdx.x;
    const int lane = tid & 31, w = tid >> 5;
    const int g = lane >> 2, tig = lane & 3;
    const int h  = blockIdx.y;
    const int q0 = blockIdx.x * 128;

    const uint32_t smb = smem_u32(sm16);
    const uint32_t qfb = smb + ATT_Q;
    const uint32_t lqs_b = smb + ATT_LQ;
    float* lqs = (float*)((char*)sm16 + ATT_LQ);

    // ---- prologue: Q + KV tile 0 ----
    #pragma unroll
    for (int u = 0; u < 4; u++) {
        int idx = tid + u * 256;
        int r = idx >> 3, c4 = idx & 7;
        size_t gofs = (size_t)(q0 + r) * CIN + h * HD + c4 * 8;
        uint32_t so = (uint32_t)((r * 72 + c4 * 8) * 2);
        cp16(qfb + so, (const uint16_t*)g_qf + gofs);
    }

    auto stage_kv = [&](int kt) {
        uint32_t sb = smb + (kt & 1) * ATT_STG;
        #pragma unroll
        for (int u = 0; u < 4; u++) {
            int idx = tid + u * 256;
            int r = idx >> 3, c4 = idx & 7;
            size_t gofs = (size_t)(kt * 128 + r) * CIN + h * HD + c4 * 8;
            uint32_t so = (uint32_t)((r * 72 + c4 * 8) * 2);
            cp16(sb + so,          (const uint16_t*)g_kf + gofs);
            cp16(sb + ATT_VF + so, (const uint16_t*)g_vf + gofs);
        }
        if (tid < 128) cp4(lqs_b + ((kt & 1) * 128 + tid) * 4, g_lq2 + kt * 128 + tid);
    };

    stage_kv(0);
    cp_commit();
    cp_wait<0>();      // Q + KV0 arrived
    __syncthreads();

    // extract Q A-fragments to registers
    uint32_t qa[4][4];
    {
        int qrow = (lane & 7) + ((lane >> 3) & 1) * 8;
        int qcol = ((lane >> 4) & 1) * 8;
        #pragma unroll
        for (int ks = 0; ks < 4; ks++) {
            uint32_t off = (uint32_t)(((w * 16 + qrow) * 72 + ks * 16 + qcol) * 2);
            uint4 a = ldsm_x4(qfb + off);
            qa[ks][0] = a.x; qa[ks][1] = a.y; qa[ks][2] = a.z; qa[ks][3] = a.w;
        }
    }

    const int krow = ((lane >> 4) & 1) * 8 + (lane & 7);
    const int kcol = ((lane >> 3) & 1) * 8;
    const int vrow = ((lane >> 3) & 1) * 8 + (lane & 7);
    const int vcol = ((lane >> 4) & 1) * 8;

    float O[8][4] = {};
    float l0 = 0.f, l1 = 0.f;

    #pragma unroll 1
    for (int kt = 0; kt < NTOK / 128; kt++) {
        __syncthreads();
        if (kt + 1 < NTOK / 128) {
            stage_kv(kt + 1);
            cp_commit();
            cp_wait<1>();
        } else {
            cp_wait<0>();
        }
        __syncthreads();

        const uint32_t sb  = smb + (kt & 1) * ATT_STG;
        const uint32_t kfb = sb, vfb = sb + ATT_VF;
        const float* lq = lqs + (kt & 1) * 128;

        // two 64-key halves (keeps registers <= 128 for occ 2)
        #pragma unroll
        for (int half = 0; half < 2; half++) {
            // ---- S = Q K^T (single fp16 term) ----
            float s[8][4] = {};
            #pragma unroll
            for (int ks = 0; ks < 4; ks++) {
                #pragma unroll
                for (int np = 0; np < 4; np++) {
                    int npp = half * 4 + np;
                    uint32_t off = (uint32_t)(((npp * 16 + krow) * 72 + ks * 16 + kcol) * 2);
                    uint4 B = ldsm_x4(kfb + off);
                    mma_f16(s[2*np],   qa[ks], B.x, B.y);
                    mma_f16(s[2*np+1], qa[ks], B.z, B.w);
                }
            }

            // ---- fused softmax (MUFU ex2) + PV ----
            const float* lqh = lq + half * 64;
            #pragma unroll
            for (int c = 0; c < 4; c++) {
                uint32_t a[4];
                {
                    const int n = 2 * c;
                    float2 lw = *(const float2*)&lqh[n * 8 + 2 * tig];
                    float p0 = ex2f(fmaf(s[n][0], SCALE_LOG2E, lw.x));
                    float p1 = ex2f(fmaf(s[n][1], SCALE_LOG2E, lw.y));
                    float p2 = ex2f(fmaf(s[n][2], SCALE_LOG2E, lw.x));
                    float p3 = ex2f(fmaf(s[n][3], SCALE_LOG2E, lw.y));
                    l0 += p0 + p1;
                    l1 += p2 + p3;
                    a[0] = packf16(p0, p1);
                    a[1] = packf16(p2, p3);
                }
                {
                    const int n = 2 * c + 1;
                    float2 lw = *(const float2*)&lqh[n * 8 + 2 * tig];
                    float p0 = ex2f(fmaf(s[n][0], SCALE_LOG2E, lw.x));
                    float p1 = ex2f(fmaf(s[n][1], SCALE_LOG2E, lw.y));
                    float p2 = ex2f(fmaf(s[n][2], SCALE_LOG2E, lw.x));
                    float p3 = ex2f(fmaf(s[n][3], SCALE_LOG2E, lw.y));
                    l0 += p0 + p1;
                    l1 += p2 + p3;
                    a[2] = packf16(p0, p1);
                    a[3] = packf16(p2, p3);
                }
                #pragma unroll
                for (int ndp = 0; ndp < 4; ndp++) {
                    uint32_t off = (uint32_t)((((half * 4 + c) * 16 + vrow) * 72 + ndp * 16 + vcol) * 2);
                    uint4 V = ldsm_x4t(vfb + off);
                    mma_f16(O[2*ndp],   a, V.x, V.y);
                    mma_f16(O[2*ndp+1], a, V.z, V.w);
                }
            }
        }
    }

    // deferred l reduction across the quad, then normalize + store fp16
    l0 += __shfl_xor_sync(0xffffffffu, l0, 1);
    l0 += __shfl_xor_sync(0xffffffffu, l0, 2);
    l1 += __shfl_xor_sync(0xffffffffu, l1, 1);
    l1 += __shfl_xor_sync(0xffffffffu, l1, 2);
    float i0 = 1.0f / l0, i1 = 1.0f / l1;

    uint16_t* of = (uint16_t*)g_of;
    #pragma unroll
    for (int nd = 0; nd < 8; nd++) {
        size_t c0 = (size_t)(q0 + w * 16 + g)     * CIN + h * HD + nd * 8 + 2 * tig;
        size_t c1 = (size_t)(q0 + w * 16 + g + 8) * CIN + h * HD + nd * 8 + 2 * tig;
        *(uint32_t*)(of + c0) = packf16(O[nd][0] * i0, O[nd][1] * i0);
        *(uint32_t*)(of + c1) = packf16(O[nd][2] * i1, O[nd][3] * i1);
    }
}

// ---------------------------------------------------------------------------
// Kernel 3: output projection, single fp16 term, 2-stage cp.async.
// Tile 128 o x 64 t -> grid (64 t-tiles, 4 o-tiles) = 256 CTAs. (unchanged)
// ---------------------------------------------------------------------------
#define PW16_OFF ((size_t)3 * CIN * CIN)
#define OP_BOF 10240
#define OP_STAGE 15360
#define OP_SMEM_BYTES (2 * OP_STAGE)   // 30720

__global__ __launch_bounds__(256, 2)
void out_proj_kernel(const float* __restrict__ pb, float* __restrict__ out)
{
    extern __shared__ uint16_t osm[];
    const uint32_t smb = smem_u32(osm);

    const int tid  = threadIdx.x;
    const int lane = tid & 31, w = tid >> 5;
    const int g = lane >> 2, tig = lane & 3;
    const int wm = w & 3, wn = w >> 2;     // wm: o quarter, wn: t half (32 each)
    const int t0 = blockIdx.x * 64;
    const int o0 = blockIdx.y * 128;

    const int arow = (lane & 7) + ((lane >> 3) & 1) * 8;
    const int acol = ((lane >> 4) & 1) * 8;
    const int brow = ((lane >> 4) & 1) * 8 + (lane & 7);
    const int bcol = ((lane >> 3) & 1) * 8;

    float C[2][4][4] = {};

    auto stage = [&](uint32_t sb, int k0) {
        #pragma unroll
        for (int u = 0; u < 2; u++) {
            int f = tid + u * 256;
            int row = f >> 2, c8 = (f & 3) * 8;
            uint32_t so = (uint32_t)((row * 40 + c8) * 2);
            size_t wofs = PW16_OFF + (size_t)(o0 + row) * CIN + k0 + c8;
            cp16(sb + so, (const uint16_t*)g_wf + wofs);
        }
        {
            int row = tid >> 2, c8 = (tid & 3) * 8;
            uint32_t so = (uint32_t)((row * 40 + c8) * 2);
            size_t aofs = (size_t)(t0 + row) * CIN + k0 + c8;
            cp16(sb + OP_BOF + so, (const uint16_t*)g_of + aofs);
        }
    };

    stage(smb, 0);
    cp_commit();

    for (int ki = 0; ki < 16; ki++) {
        __syncthreads();
        if (ki + 1 < 16) {
            stage(smb + ((ki + 1) & 1) * OP_STAGE, (ki + 1) * 32);
            cp_commit();
            cp_wait<1>();
        } else {
            cp_wait<0>();
        }
        __syncthreads();

        const uint32_t sb = smb + (ki & 1) * OP_STAGE;
        const uint32_t awf = sb, bof = sb + OP_BOF;

        #pragma unroll
        for (int ks = 0; ks < 2; ks++) {
            uint32_t A[2][4];
            #pragma unroll
            for (int mf = 0; mf < 2; mf++) {
                uint32_t off = (uint32_t)(((wm * 32 + mf * 16 + arow) * 40 + ks * 16 + acol) * 2);
                uint4 a = ldsm_x4(awf + off);
                A[mf][0] = a.x; A[mf][1] = a.y; A[mf][2] = a.z; A[mf][3] = a.w;
            }
            #pragma unroll
            for (int np = 0; np < 2; np++) {
                uint32_t off = (uint32_t)(((wn * 32 + np * 16 + brow) * 40 + ks * 16 + bcol) * 2);
                uint4 B = ldsm_x4(bof + off);
                #pragma unroll
                for (int mf = 0; mf < 2; mf++) {
                    mma_f16(C[mf][2*np],   A[mf], B.x, B.y);
                    mma_f16(C[mf][2*np+1], A[mf], B.z, B.w);
                }
            }
        }
    }

    #pragma unroll
    for (int mf = 0; mf < 2; mf++) {
        int orow0 = o0 + wm * 32 + mf * 16 + g;
        float b0 = pb[orow0], b1 = pb[orow0 + 8];
        #pragma unroll
        for (int n = 0; n < 4; n++) {
            int tcol = t0 + wn * 32 + n * 8 + 2 * tig;
            const float* c = C[mf][n];
            float2 r0; r0.x = c[0] + b0; r0.y = c[1] + b0;
            float2 r1; r1.x = c[2] + b1; r1.y = c[3] + b1;
            *(float2*)&out[(size_t)orow0 * NTOK + tcol]       = r0;
            *(float2*)&out[(size_t)(orow0 + 8) * NTOK + tcol] = r1;
        }
    }
}

// ---------------------------------------------------------------------------
extern "C" void kernel_launch(void* const* d_in, const int* in_sizes, int n_in,
                              void* d_out, int out_size)
{
    (void)in_sizes; (void)n_in; (void)out_size;
    const float* x   = (const float*)d_in[0];
    const float* qw  = (const float*)d_in[1];
    const float* qb  = (const float*)d_in[2];
    const float* kw  = (const float*)d_in[3];
    const float* kb  = (const float*)d_in[4];
    const float* vw  = (const float*)d_in[5];
    const float* vb  = (const float*)d_in[6];
    const float* pw  = (const float*)d_in[7];
    const float* pb  = (const float*)d_in[8];
    const float* lqw = (const float*)d_in[9];
    float* out = (float*)d_out;

    cudaFuncSetAttribute(qkv_proj_kernel, cudaFuncAttributeMaxDynamicSharedMemorySize,
                         QKV_SMEM_BYTES);
    cudaFuncSetAttribute(attn_kernel, cudaFuncAttributeMaxDynamicSharedMemorySize,
                         ATTN_SMEM_BYTES);
    cudaFuncSetAttribute(out_proj_kernel, cudaFuncAttributeMaxDynamicSharedMemorySize,
                         OP_SMEM_BYTES);

    convert_kernel<<<(NCONV + 255) / 256, 256>>>(x, qw, kw, vw, pw, lqw);
    qkv_proj_kernel<<<dim3(NTOK / 128, 12), 256, QKV_SMEM_BYTES>>>(qb, kb, vb);
    attn_kernel<<<dim3(NTOK / 128, HEADS), 256, ATTN_SMEM_BYTES>>>();
    out_proj_kernel<<<dim3(NTOK / 64, CIN / 128), 256, OP_SMEM_BYTES>>>(pb, out);
}